// round 1
// baseline (speedup 1.0000x reference)
#include <cuda_runtime.h>
#include <math.h>

#define N_NODES 20000
#define E_EDGES 640000
#define INF_C 100000.0f
#define CH_E 32

// -------- device scratch (no allocations allowed) --------
__device__ __align__(16) float g_q[N_NODES * 128];
__device__ __align__(16) float g_kv[N_NODES * 128];
__device__ __align__(16) float g_qp[N_NODES * 192];
__device__ __align__(16) float g_kp[N_NODES * 24];
__device__ __align__(16) float g_kp2[N_NODES * 8];
__device__ __align__(16) float g_qsum[N_NODES * 24];
__device__ __align__(16) float g_sq[N_NODES * 8];
__device__ __align__(16) float g_feats[N_NODES * 416];
__device__ int g_deg[N_NODES];
__device__ int g_off[N_NODES + 1];
__device__ int g_fill[N_NODES];
__device__ int g_sorted[E_EDGES];

// -------- sort-by-src kernels --------
__global__ void zero_int_kernel() {
    int t = blockIdx.x * blockDim.x + threadIdx.x;
    if (t < N_NODES) { g_deg[t] = 0; g_fill[t] = 0; }
}

__global__ void hist_kernel(const int* __restrict__ ei) {
    int e = blockIdx.x * blockDim.x + threadIdx.x;
    if (e < E_EDGES) atomicAdd(&g_deg[ei[E_EDGES + e]], 1);
}

__global__ void scan_kernel() {
    __shared__ int sv[1024];
    __shared__ int sCarry;
    int t = threadIdx.x;
    if (t == 0) { sCarry = 0; g_off[0] = 0; }
    __syncthreads();
    for (int base = 0; base < N_NODES; base += 1024) {
        int v = (base + t < N_NODES) ? g_deg[base + t] : 0;
        sv[t] = v;
        __syncthreads();
        for (int o = 1; o < 1024; o <<= 1) {
            int add = (t >= o) ? sv[t - o] : 0;
            __syncthreads();
            sv[t] += add;
            __syncthreads();
        }
        int cb = sCarry;
        if (base + t < N_NODES) g_off[base + t + 1] = cb + sv[t];
        __syncthreads();
        if (t == 1023) sCarry = cb + sv[1023];
        __syncthreads();
    }
}

__global__ void scatter_kernel(const int* __restrict__ ei) {
    int e = blockIdx.x * blockDim.x + threadIdx.x;
    if (e < E_EDGES) {
        int s = ei[E_EDGES + e];
        int p = g_off[s] + atomicAdd(&g_fill[s], 1);
        g_sorted[p] = e;
    }
}

// -------- generic tiled SGEMM: C[M,Nc] = A[M,Kc](lda) @ B[Kc,Nc] + bias --------
__global__ __launch_bounds__(256) void sgemm_kernel(
    const float* __restrict__ A, const float* __restrict__ B,
    const float* __restrict__ bias, float* __restrict__ C,
    int M, int Nc, int Kc, int lda)
{
    __shared__ __align__(16) float As[8][128];
    __shared__ __align__(16) float Bs[8][128];
    int tid = threadIdx.x;
    int bm = blockIdx.y * 128;
    int bn = blockIdx.x * 128;
    int ty = tid >> 4;       // 0..15
    int tx = tid & 15;       // 0..15
    float acc[8][8];
#pragma unroll
    for (int i = 0; i < 8; i++)
#pragma unroll
        for (int j = 0; j < 8; j++) acc[i][j] = 0.f;

    int arow = tid >> 1;          // 0..127
    int acol = (tid & 1) * 4;     // 0 or 4
    int brow = tid >> 5;          // 0..7
    int bcol = (tid & 31) * 4;    // 0..124

    for (int k0 = 0; k0 < Kc; k0 += 8) {
        float4 av = make_float4(0.f, 0.f, 0.f, 0.f);
        int gr = bm + arow;
        if (gr < M) av = *(const float4*)&A[(size_t)gr * lda + k0 + acol];
        As[acol + 0][arow] = av.x;
        As[acol + 1][arow] = av.y;
        As[acol + 2][arow] = av.z;
        As[acol + 3][arow] = av.w;
        float4 bv = make_float4(0.f, 0.f, 0.f, 0.f);
        int gc = bn + bcol;
        if (gc < Nc) bv = *(const float4*)&B[(size_t)(k0 + brow) * Nc + gc];
        *(float4*)&Bs[brow][bcol] = bv;
        __syncthreads();
#pragma unroll
        for (int kk = 0; kk < 8; kk++) {
            float a[8], b[8];
#pragma unroll
            for (int i = 0; i < 8; i++) a[i] = As[kk][ty * 8 + i];
#pragma unroll
            for (int j = 0; j < 8; j++) b[j] = Bs[kk][tx * 8 + j];
#pragma unroll
            for (int i = 0; i < 8; i++)
#pragma unroll
                for (int j = 0; j < 8; j++) acc[i][j] += a[i] * b[j];
        }
        __syncthreads();
    }
#pragma unroll
    for (int i = 0; i < 8; i++) {
        int r = bm + ty * 8 + i;
        if (r >= M) continue;
#pragma unroll
        for (int j = 0; j < 8; j++) {
            int cc = bn + tx * 8 + j;
            if (cc < Nc) C[(size_t)r * Nc + cc] = acc[i][j] + (bias ? bias[cc] : 0.f);
        }
    }
}

// -------- per-node small precompute: k_vec permutation + rotated q-point sums --------
__global__ void nodeprep_kernel(const float* __restrict__ tfn, const float* __restrict__ Wkv,
                                const float* __restrict__ rot, const float* __restrict__ trans)
{
    int i = blockIdx.x, t = threadIdx.x;   // 64 threads
    __shared__ float skv[24], skp[24], sR[9], sT[3];
    if (t < 9) sR[t] = rot[i * 9 + t];
    if (t < 3) sT[t] = trans[i * 3 + t];
    if (t < 24) {
        int q = t / 3, x = t % 3;
        float s = 0.f;
#pragma unroll
        for (int p = 0; p < 16; p++)
            s += tfn[(size_t)i * 176 + 128 + p * 3 + x] * Wkv[p * 8 + q];
        skv[t] = s;
    }
    __syncthreads();
    if (t < 24) {
        // k_pts[h][x]: flat = 3h+x = t ; a=t/8, b=t%8 -> kvec element b*3+a
        int a = t >> 3, b = t & 7;
        float v = skv[b * 3 + a];
        skp[t] = v;
        g_kp[i * 24 + t] = v;
    }
    __syncthreads();
    if (t < 8) {
        float x = skp[t * 3], y = skp[t * 3 + 1], zc = skp[t * 3 + 2];
        g_kp2[i * 8 + t] = x * x + y * y + zc * zc;
    }
    // q_pts: 64 points; pre[x] = qp[x*64+p]; rotated r = R*pre + t; head h = p>>3
    {
        int p = t;
        float p0 = g_qp[(size_t)i * 192 + p];
        float p1 = g_qp[(size_t)i * 192 + 64 + p];
        float p2 = g_qp[(size_t)i * 192 + 128 + p];
        float rx = sR[0] * p0 + sR[1] * p1 + sR[2] * p2 + sT[0];
        float ry = sR[3] * p0 + sR[4] * p1 + sR[5] * p2 + sT[1];
        float rz = sR[6] * p0 + sR[7] * p1 + sR[8] * p2 + sT[2];
        float sq = rx * rx + ry * ry + rz * rz;
#pragma unroll
        for (int o = 4; o > 0; o >>= 1) {
            rx += __shfl_down_sync(0xffffffffu, rx, o, 8);
            ry += __shfl_down_sync(0xffffffffu, ry, o, 8);
            rz += __shfl_down_sync(0xffffffffu, rz, o, 8);
            sq += __shfl_down_sync(0xffffffffu, sq, o, 8);
        }
        if ((t & 7) == 0) {
            int h = t >> 3;
            g_qsum[i * 24 + h * 3 + 0] = rx;
            g_qsum[i * 24 + h * 3 + 1] = ry;
            g_qsum[i * 24 + h * 3 + 2] = rz;
            g_sq[i * 8 + h] = sq;
        }
    }
}

// -------- main edge kernel: one CTA per src node, chunked online softmax --------
__global__ __launch_bounds__(256, 2) void edge_kernel(
    const float* __restrict__ z, const int* __restrict__ ei,
    const float* __restrict__ mask, const float* __restrict__ rot,
    const float* __restrict__ trans, const float* __restrict__ Wb,
    const float* __restrict__ bb, const float* __restrict__ Wdz,
    const float* __restrict__ bdz, const float* __restrict__ hwraw)
{
    __shared__ __align__(16) float bufA[8192];   // phase: sZ[0..4096) sK[4096..8192); epilogue reuses
    __shared__ float sKp[CH_E * 24];
    __shared__ float sKp2[CH_E * 8];
    __shared__ float sLogit[CH_E * 8];
    __shared__ float sQ[128], sQsum[24], sSq[8], sHwn[8], sBB[8], sR[9], sT[3];
    __shared__ float sM[8], sScale[8], sMaskSrc;

    const int i = blockIdx.x;
    const int t = threadIdx.x;
    const int wid = t >> 5, lane = t & 31;
    float* sZ = bufA;
    float* sK = bufA + CH_E * 128;

    if (t < 128) sQ[t] = g_q[(size_t)i * 128 + t];
    if (t < 24) sQsum[t] = g_qsum[i * 24 + t];
    if (t < 8) {
        sSq[t] = g_sq[i * 8 + t];
        float r = hwraw[t];
        sHwn[t] = -0.5f * log1pf(expf(r)) * sqrtf(1.f / 108.f);
        sBB[t] = bb[t];
        sM[t] = -3.0e38f;
    }
    if (t >= 32 && t < 41) sR[t - 32] = rot[i * 9 + (t - 32)];
    if (t >= 48 && t < 51) sT[t - 48] = trans[i * 3 + (t - 48)];
    if (t == 0) sMaskSrc = mask[i];

    // Wb rows 4*lane..4*lane+3 cached in registers (reused every edge)
    float Wbr[4][8];
#pragma unroll
    for (int j = 0; j < 4; j++)
#pragma unroll
        for (int h = 0; h < 8; h++)
            Wbr[j][h] = Wb[(4 * lane + j) * 8 + h];

    // register accumulators
    float za0 = 0.f, za1 = 0.f, za2 = 0.f, za3 = 0.f;  // zacc[wid][lane*4..]
    float oAcc = 0.f, pAcc = 0.f, sAcc = 0.f;
    const int off0 = g_off[i];
    const int deg = g_off[i + 1] - off0;
    __syncthreads();

    const float C1 = sqrtf(1.f / 48.f), C2 = sqrtf(1.f / 3.f);

    for (int done = 0; done < deg; done += CH_E) {
        int c = min(CH_E, deg - done);
        // ---- phase A: logits + stash z,k,kp ----
        for (int le = wid; le < c; le += 8) {
            int e = g_sorted[off0 + done + le];
            int dst = ei[e];
            float4 zv = *(const float4*)&z[(size_t)e * 128 + lane * 4];
            *(float4*)&sZ[le * 128 + lane * 4] = zv;
            float4 kv = *(const float4*)&g_kv[(size_t)dst * 128 + lane * 4];
            *(float4*)&sK[le * 128 + lane * 4] = kv;
            float bp[8];
#pragma unroll
            for (int h = 0; h < 8; h++)
                bp[h] = zv.x * Wbr[0][h] + zv.y * Wbr[1][h] + zv.z * Wbr[2][h] + zv.w * Wbr[3][h];
#pragma unroll
            for (int o = 16; o > 0; o >>= 1)
#pragma unroll
                for (int h = 0; h < 8; h++)
                    bp[h] += __shfl_xor_sync(0xffffffffu, bp[h], o);
            float4 qv = *(const float4*)&sQ[lane * 4];
            float qk = kv.x * qv.x + kv.y * qv.y + kv.z * qv.z + kv.w * qv.w;
            qk += __shfl_xor_sync(0xffffffffu, qk, 1);
            qk += __shfl_xor_sync(0xffffffffu, qk, 2);
            float qkh = __shfl_sync(0xffffffffu, qk, (lane & 7) * 4);
            if (lane < 24) sKp[le * 24 + lane] = g_kp[dst * 24 + lane];
            else sKp2[le * 8 + (lane - 24)] = g_kp2[dst * 8 + (lane - 24)];
            float md = mask[dst];
            __syncwarp();
            if (lane < 8) {
                int h = lane;
                float kx = sKp[le * 24 + h * 3], ky = sKp[le * 24 + h * 3 + 1], kz = sKp[le * 24 + h * 3 + 2];
                float pt = sHwn[h] * (sSq[h]
                           - 2.f * (sQsum[h * 3] * kx + sQsum[h * 3 + 1] * ky + sQsum[h * 3 + 2] * kz)
                           + 8.f * sKp2[le * 8 + h]);
                float logit = C1 * qkh + C2 * (bp[h] + sBB[h]) + pt
                            + INF_C * (sMaskSrc * md - 1.f);
                sLogit[le * 8 + h] = logit;
            }
        }
        __syncthreads();
        // ---- chunk max + rescale factors ----
        if (t < 8) {
            float cm = -3.0e38f;
            for (int le = 0; le < c; le++) cm = fmaxf(cm, sLogit[le * 8 + t]);
            float nm = fmaxf(sM[t], cm);
            sScale[t] = expf(sM[t] - nm);
            sM[t] = nm;
        }
        __syncthreads();
        {
            float sc = sScale[wid];
            za0 *= sc; za1 *= sc; za2 *= sc; za3 *= sc;
            if (t < 128) oAcc *= sScale[t >> 4];
            if (t < 24)  pAcc *= sScale[t / 3];
            if (t < 8)   sAcc *= sScale[t];
        }
        if (t < c * 8) sLogit[t] = expf(sLogit[t] - sM[t & 7]);
        __syncthreads();
        // ---- phase B: weighted accumulation (register-owned, no atomics) ----
#pragma unroll 2
        for (int le = 0; le < c; le++) {
            float w = sLogit[le * 8 + wid];
            float4 zv = *(const float4*)&sZ[le * 128 + lane * 4];
            za0 += w * zv.x; za1 += w * zv.y; za2 += w * zv.z; za3 += w * zv.w;
            if (t < 128) oAcc += sLogit[le * 8 + (t >> 4)] * sK[le * 128 + t];
            if (t < 24)  pAcc += sLogit[le * 8 + t / 3] * sKp[le * 24 + t];
            if (t < 8)   sAcc += sLogit[le * 8 + t];
        }
        __syncthreads();
    }

    // ---- epilogue: normalize, inverse-rotate points, zacc @ Wdz, write feats ----
    float* sWdz  = bufA;            // 4096 floats
    float* sAccZ = bufA + 4096;     // 1024
    float* sF    = bufA + 5120;     // 416
    float* sAccO = bufA + 5536;     // 128
    float* sAccP = bufA + 5664;     // 24
    float* sSv   = bufA + 5688;     // 8
    float* sInv  = bufA + 5696;     // 8
    float* sSa   = bufA + 5704;     // 8

    ((float4*)sAccZ)[t] = make_float4(za0, za1, za2, za3);
    if (t < 128) sAccO[t] = oAcc;
    if (t < 24)  sAccP[t] = pAcc;
    if (t < 8)   sSv[t] = sAcc;
#pragma unroll
    for (int r = 0; r < 4; r++)
        ((float4*)sWdz)[t + r * 256] = ((const float4*)Wdz)[t + r * 256];
    __syncthreads();
    if (t < 8) {
        float inv = 1.f / (sSv[t] + 1e-16f);
        sInv[t] = inv;
        sSa[t] = sSv[t] * inv;
    }
    __syncthreads();
    if (t < 128) sF[t] = sAccO[t] * sInv[t >> 4];
    if (t < 8) {
        int h = t;
        float gx = sAccP[h * 3 + 0] * sInv[h] - sT[0];
        float gy = sAccP[h * 3 + 1] * sInv[h] - sT[1];
        float gz = sAccP[h * 3 + 2] * sInv[h] - sT[2];
        float lx = sR[0] * gx + sR[3] * gy + sR[6] * gz;   // R^T * g
        float ly = sR[1] * gx + sR[4] * gy + sR[7] * gz;
        float lz = sR[2] * gx + sR[5] * gy + sR[8] * gz;
        sF[128 + h] = lx; sF[136 + h] = ly; sF[144 + h] = lz;
        sF[152 + h] = sqrtf(lx * lx + ly * ly + lz * lz + 1e-8f);
    }
    {
        int h = wid, j = lane;
        float dot = 0.f;
#pragma unroll 8
        for (int cc = 0; cc < 128; cc++) dot += sAccZ[h * 128 + cc] * sWdz[cc * 32 + j];
        sF[160 + t] = dot * sInv[h] + sSa[h] * bdz[j];
    }
    __syncthreads();
    for (int idx = t; idx < 416; idx += 256)
        g_feats[(size_t)i * 416 + idx] = sF[idx];
}

// -------- launch --------
extern "C" void kernel_launch(void* const* d_in, const int* in_sizes, int n_in,
                              void* d_out, int out_size) {
    const float* frame_s = (const float*)d_in[0];
    const float* tfn     = (const float*)d_in[1];
    const float* z       = (const float*)d_in[2];
    const int*   ei      = (const int*)d_in[3];
    const float* mask    = (const float*)d_in[4];
    const float* rot     = (const float*)d_in[5];
    const float* trans   = (const float*)d_in[6];
    const float* Wq      = (const float*)d_in[7];
    const float* bq      = (const float*)d_in[8];
    const float* Wks     = (const float*)d_in[9];
    const float* Wkv     = (const float*)d_in[10];
    const float* Wqp     = (const float*)d_in[11];
    const float* bqp     = (const float*)d_in[12];
    const float* Wb      = (const float*)d_in[13];
    const float* bb      = (const float*)d_in[14];
    const float* Wdz     = (const float*)d_in[15];
    const float* bdz     = (const float*)d_in[16];
    const float* hw      = (const float*)d_in[17];
    const float* Wout    = (const float*)d_in[18];
    const float* bout    = (const float*)d_in[19];
    float* out = (float*)d_out;

    void *pq, *pqp, *pkv, *pfeats;
    cudaGetSymbolAddress(&pq, g_q);
    cudaGetSymbolAddress(&pqp, g_qp);
    cudaGetSymbolAddress(&pkv, g_kv);
    cudaGetSymbolAddress(&pfeats, g_feats);

    zero_int_kernel<<<(N_NODES + 255) / 256, 256>>>();
    hist_kernel<<<(E_EDGES + 255) / 256, 256>>>(ei);
    scan_kernel<<<1, 1024>>>();
    scatter_kernel<<<(E_EDGES + 255) / 256, 256>>>(ei);

    dim3 blk(256);
    int gy = (N_NODES + 127) / 128;   // 157
    sgemm_kernel<<<dim3(1, gy), blk>>>(frame_s, Wq,  bq,   (float*)pq,     N_NODES, 128, 384, 384);
    sgemm_kernel<<<dim3(2, gy), blk>>>(frame_s, Wqp, bqp,  (float*)pqp,    N_NODES, 192, 384, 384);
    sgemm_kernel<<<dim3(1, gy), blk>>>(tfn,     Wks, 0,    (float*)pkv,    N_NODES, 128, 128, 176);
    nodeprep_kernel<<<N_NODES, 64>>>(tfn, Wkv, rot, trans);
    edge_kernel<<<N_NODES, 256>>>(z, ei, mask, rot, trans, Wb, bb, Wdz, bdz, hw);
    sgemm_kernel<<<dim3(3, gy), blk>>>((const float*)pfeats, Wout, bout, out, N_NODES, 384, 416, 416);
}

// round 2
// speedup vs baseline: 1.0550x; 1.0550x over previous
#include <cuda_runtime.h>
#include <math.h>

#define N_NODES 20000
#define E_EDGES 640000
#define INF_C 100000.0f
#define CH_E 32

// -------- device scratch (no allocations allowed) --------
__device__ __align__(16) float g_q[N_NODES * 128];
__device__ __align__(16) float g_kv[N_NODES * 128];
__device__ __align__(16) float g_qp[N_NODES * 192];
__device__ __align__(16) float g_kp[N_NODES * 24];
__device__ __align__(16) float g_kp2[N_NODES * 8];
__device__ __align__(16) float g_qsum[N_NODES * 24];
__device__ __align__(16) float g_sq[N_NODES * 8];
__device__ __align__(16) float g_feats[N_NODES * 416];
__device__ int g_deg[N_NODES];
__device__ int g_off[N_NODES + 1];
__device__ int g_fill[N_NODES];
__device__ int g_sorted[E_EDGES];

// -------- sort-by-src kernels --------
__global__ void zero_int_kernel() {
    int t = blockIdx.x * blockDim.x + threadIdx.x;
    if (t < N_NODES) { g_deg[t] = 0; g_fill[t] = 0; }
}

__global__ void hist_kernel(const int* __restrict__ ei) {
    int e = blockIdx.x * blockDim.x + threadIdx.x;
    if (e < E_EDGES) atomicAdd(&g_deg[ei[E_EDGES + e]], 1);
}

__global__ void scan_kernel() {
    __shared__ int sv[1024];
    __shared__ int sCarry;
    int t = threadIdx.x;
    if (t == 0) { sCarry = 0; g_off[0] = 0; }
    __syncthreads();
    for (int base = 0; base < N_NODES; base += 1024) {
        int v = (base + t < N_NODES) ? g_deg[base + t] : 0;
        sv[t] = v;
        __syncthreads();
        for (int o = 1; o < 1024; o <<= 1) {
            int add = (t >= o) ? sv[t - o] : 0;
            __syncthreads();
            sv[t] += add;
            __syncthreads();
        }
        int cb = sCarry;
        if (base + t < N_NODES) g_off[base + t + 1] = cb + sv[t];
        __syncthreads();
        if (t == 1023) sCarry = cb + sv[1023];
        __syncthreads();
    }
}

__global__ void scatter_kernel(const int* __restrict__ ei) {
    int e = blockIdx.x * blockDim.x + threadIdx.x;
    if (e < E_EDGES) {
        int s = ei[E_EDGES + e];
        int p = g_off[s] + atomicAdd(&g_fill[s], 1);
        g_sorted[p] = e;
    }
}

// -------- double-buffered tiled SGEMM: C[M,Nc] = A[M,Kc](lda) @ B[Kc,Nc] + bias --------
// 128x128 tile, BK=16, 256 threads, 8x8 per thread (rows r0..r0+3,r0+64..+67; cols likewise)
__global__ __launch_bounds__(256) void sgemm_kernel(
    const float* __restrict__ A, const float* __restrict__ B,
    const float* __restrict__ bias, float* __restrict__ C,
    int M, int Nc, int Kc, int lda)
{
    __shared__ __align__(16) float As[2][16][132];
    __shared__ __align__(16) float Bs[2][16][132];
    const int tid = threadIdx.x;
    const int bm = blockIdx.y * 128;
    const int bn = blockIdx.x * 128;
    const int ty = tid >> 4;        // 0..15
    const int tx = tid & 15;        // 0..15

    // load indices
    const int aRow = tid >> 2;            // 0..63
    const int aCol = (tid & 3) << 2;      // 0,4,8,12
    const int bRow = tid >> 4;            // 0..15
    const int bCol = (tid & 15) << 2;     // 0..60

    const bool aOk0 = (bm + aRow) < M;
    const bool aOk1 = (bm + aRow + 64) < M;
    const bool bOk0 = (bn + bCol) < Nc;
    const bool bOk1 = (bn + bCol + 64) < Nc;
    const float4 z4 = make_float4(0.f, 0.f, 0.f, 0.f);

    float acc[8][8];
#pragma unroll
    for (int i = 0; i < 8; i++)
#pragma unroll
        for (int j = 0; j < 8; j++) acc[i][j] = 0.f;

    const int nTiles = Kc >> 4;

    // prefetch tile 0
    float4 pa0 = z4, pa1 = z4, pb0 = z4, pb1 = z4;
    {
        if (aOk0) pa0 = *(const float4*)&A[(size_t)(bm + aRow) * lda + aCol];
        if (aOk1) pa1 = *(const float4*)&A[(size_t)(bm + aRow + 64) * lda + aCol];
        if (bOk0) pb0 = *(const float4*)&B[(size_t)bRow * Nc + bn + bCol];
        if (bOk1) pb1 = *(const float4*)&B[(size_t)bRow * Nc + bn + bCol + 64];
    }
    // store tile 0
    {
        As[0][aCol + 0][aRow] = pa0.x; As[0][aCol + 1][aRow] = pa0.y;
        As[0][aCol + 2][aRow] = pa0.z; As[0][aCol + 3][aRow] = pa0.w;
        As[0][aCol + 0][aRow + 64] = pa1.x; As[0][aCol + 1][aRow + 64] = pa1.y;
        As[0][aCol + 2][aRow + 64] = pa1.z; As[0][aCol + 3][aRow + 64] = pa1.w;
        *(float4*)&Bs[0][bRow][bCol] = pb0;
        *(float4*)&Bs[0][bRow][bCol + 64] = pb1;
    }
    __syncthreads();

    for (int tile = 0; tile < nTiles; tile++) {
        const int cur = tile & 1;
        // prefetch next tile into registers
        if (tile + 1 < nTiles) {
            const int k0 = (tile + 1) << 4;
            pa0 = z4; pa1 = z4; pb0 = z4; pb1 = z4;
            if (aOk0) pa0 = *(const float4*)&A[(size_t)(bm + aRow) * lda + k0 + aCol];
            if (aOk1) pa1 = *(const float4*)&A[(size_t)(bm + aRow + 64) * lda + k0 + aCol];
            if (bOk0) pb0 = *(const float4*)&B[(size_t)(k0 + bRow) * Nc + bn + bCol];
            if (bOk1) pb1 = *(const float4*)&B[(size_t)(k0 + bRow) * Nc + bn + bCol + 64];
        }
        // compute on current buffer
#pragma unroll
        for (int kk = 0; kk < 16; kk++) {
            float4 a0 = *(const float4*)&As[cur][kk][ty * 4];
            float4 a1 = *(const float4*)&As[cur][kk][ty * 4 + 64];
            float4 b0 = *(const float4*)&Bs[cur][kk][tx * 4];
            float4 b1 = *(const float4*)&Bs[cur][kk][tx * 4 + 64];
            float av[8] = {a0.x, a0.y, a0.z, a0.w, a1.x, a1.y, a1.z, a1.w};
            float bv[8] = {b0.x, b0.y, b0.z, b0.w, b1.x, b1.y, b1.z, b1.w};
#pragma unroll
            for (int i = 0; i < 8; i++)
#pragma unroll
                for (int j = 0; j < 8; j++) acc[i][j] += av[i] * bv[j];
        }
        // store prefetched tile into other buffer
        if (tile + 1 < nTiles) {
            const int nxt = cur ^ 1;
            As[nxt][aCol + 0][aRow] = pa0.x; As[nxt][aCol + 1][aRow] = pa0.y;
            As[nxt][aCol + 2][aRow] = pa0.z; As[nxt][aCol + 3][aRow] = pa0.w;
            As[nxt][aCol + 0][aRow + 64] = pa1.x; As[nxt][aCol + 1][aRow + 64] = pa1.y;
            As[nxt][aCol + 2][aRow + 64] = pa1.z; As[nxt][aCol + 3][aRow + 64] = pa1.w;
            *(float4*)&Bs[nxt][bRow][bCol] = pb0;
            *(float4*)&Bs[nxt][bRow][bCol + 64] = pb1;
        }
        __syncthreads();
    }

    // epilogue
#pragma unroll
    for (int i = 0; i < 8; i++) {
        int r = bm + ((i < 4) ? (ty * 4 + i) : (ty * 4 + 64 + i - 4));
        if (r >= M) continue;
#pragma unroll
        for (int j = 0; j < 8; j++) {
            int cc = bn + ((j < 4) ? (tx * 4 + j) : (tx * 4 + 64 + j - 4));
            if (cc < Nc) C[(size_t)r * Nc + cc] = acc[i][j] + (bias ? bias[cc] : 0.f);
        }
    }
}

// -------- per-node small precompute: k_vec permutation + rotated q-point sums --------
__global__ void nodeprep_kernel(const float* __restrict__ tfn, const float* __restrict__ Wkv,
                                const float* __restrict__ rot, const float* __restrict__ trans)
{
    int i = blockIdx.x, t = threadIdx.x;   // 64 threads
    __shared__ float skv[24], skp[24], sR[9], sT[3];
    if (t < 9) sR[t] = rot[i * 9 + t];
    if (t < 3) sT[t] = trans[i * 3 + t];
    if (t < 24) {
        int q = t / 3, x = t % 3;
        float s = 0.f;
#pragma unroll
        for (int p = 0; p < 16; p++)
            s += tfn[(size_t)i * 176 + 128 + p * 3 + x] * Wkv[p * 8 + q];
        skv[t] = s;
    }
    __syncthreads();
    if (t < 24) {
        int a = t >> 3, b = t & 7;
        float v = skv[b * 3 + a];
        skp[t] = v;
        g_kp[i * 24 + t] = v;
    }
    __syncthreads();
    if (t < 8) {
        float x = skp[t * 3], y = skp[t * 3 + 1], zc = skp[t * 3 + 2];
        g_kp2[i * 8 + t] = x * x + y * y + zc * zc;
    }
    {
        int p = t;
        float p0 = g_qp[(size_t)i * 192 + p];
        float p1 = g_qp[(size_t)i * 192 + 64 + p];
        float p2 = g_qp[(size_t)i * 192 + 128 + p];
        float rx = sR[0] * p0 + sR[1] * p1 + sR[2] * p2 + sT[0];
        float ry = sR[3] * p0 + sR[4] * p1 + sR[5] * p2 + sT[1];
        float rz = sR[6] * p0 + sR[7] * p1 + sR[8] * p2 + sT[2];
        float sq = rx * rx + ry * ry + rz * rz;
#pragma unroll
        for (int o = 4; o > 0; o >>= 1) {
            rx += __shfl_down_sync(0xffffffffu, rx, o, 8);
            ry += __shfl_down_sync(0xffffffffu, ry, o, 8);
            rz += __shfl_down_sync(0xffffffffu, rz, o, 8);
            sq += __shfl_down_sync(0xffffffffu, sq, o, 8);
        }
        if ((t & 7) == 0) {
            int h = t >> 3;
            g_qsum[i * 24 + h * 3 + 0] = rx;
            g_qsum[i * 24 + h * 3 + 1] = ry;
            g_qsum[i * 24 + h * 3 + 2] = rz;
            g_sq[i * 8 + h] = sq;
        }
    }
}

// -------- main edge kernel: one CTA per src node, chunked online softmax --------
__global__ __launch_bounds__(256, 2) void edge_kernel(
    const float* __restrict__ z, const int* __restrict__ ei,
    const float* __restrict__ mask, const float* __restrict__ rot,
    const float* __restrict__ trans, const float* __restrict__ Wb,
    const float* __restrict__ bb, const float* __restrict__ Wdz,
    const float* __restrict__ bdz, const float* __restrict__ hwraw)
{
    __shared__ __align__(16) float bufA[8192];
    __shared__ float sKp[CH_E * 24];
    __shared__ float sKp2[CH_E * 8];
    __shared__ float sLogit[CH_E * 8];
    __shared__ float sQ[128], sQsum[24], sSq[8], sHwn[8], sBB[8], sR[9], sT[3];
    __shared__ float sM[8], sScale[8], sMaskSrc;

    const int i = blockIdx.x;
    const int t = threadIdx.x;
    const int wid = t >> 5, lane = t & 31;
    float* sZ = bufA;
    float* sK = bufA + CH_E * 128;

    if (t < 128) sQ[t] = g_q[(size_t)i * 128 + t];
    if (t < 24) sQsum[t] = g_qsum[i * 24 + t];
    if (t < 8) {
        sSq[t] = g_sq[i * 8 + t];
        float r = hwraw[t];
        sHwn[t] = -0.5f * log1pf(expf(r)) * sqrtf(1.f / 108.f);
        sBB[t] = bb[t];
        sM[t] = -3.0e38f;
    }
    if (t >= 32 && t < 41) sR[t - 32] = rot[i * 9 + (t - 32)];
    if (t >= 48 && t < 51) sT[t - 48] = trans[i * 3 + (t - 48)];
    if (t == 0) sMaskSrc = mask[i];

    float Wbr[4][8];
#pragma unroll
    for (int j = 0; j < 4; j++)
#pragma unroll
        for (int h = 0; h < 8; h++)
            Wbr[j][h] = Wb[(4 * lane + j) * 8 + h];

    float za0 = 0.f, za1 = 0.f, za2 = 0.f, za3 = 0.f;
    float oAcc = 0.f, pAcc = 0.f, sAcc = 0.f;
    const int off0 = g_off[i];
    const int deg = g_off[i + 1] - off0;
    __syncthreads();

    const float C1 = sqrtf(1.f / 48.f), C2 = sqrtf(1.f / 3.f);

    for (int done = 0; done < deg; done += CH_E) {
        int c = min(CH_E, deg - done);
        for (int le = wid; le < c; le += 8) {
            int e = g_sorted[off0 + done + le];
            int dst = ei[e];
            float4 zv = *(const float4*)&z[(size_t)e * 128 + lane * 4];
            *(float4*)&sZ[le * 128 + lane * 4] = zv;
            float4 kv = *(const float4*)&g_kv[(size_t)dst * 128 + lane * 4];
            *(float4*)&sK[le * 128 + lane * 4] = kv;
            float bp[8];
#pragma unroll
            for (int h = 0; h < 8; h++)
                bp[h] = zv.x * Wbr[0][h] + zv.y * Wbr[1][h] + zv.z * Wbr[2][h] + zv.w * Wbr[3][h];
#pragma unroll
            for (int o = 16; o > 0; o >>= 1)
#pragma unroll
                for (int h = 0; h < 8; h++)
                    bp[h] += __shfl_xor_sync(0xffffffffu, bp[h], o);
            float4 qv = *(const float4*)&sQ[lane * 4];
            float qk = kv.x * qv.x + kv.y * qv.y + kv.z * qv.z + kv.w * qv.w;
            qk += __shfl_xor_sync(0xffffffffu, qk, 1);
            qk += __shfl_xor_sync(0xffffffffu, qk, 2);
            float qkh = __shfl_sync(0xffffffffu, qk, (lane & 7) * 4);
            if (lane < 24) sKp[le * 24 + lane] = g_kp[dst * 24 + lane];
            else sKp2[le * 8 + (lane - 24)] = g_kp2[dst * 8 + (lane - 24)];
            float md = mask[dst];
            __syncwarp();
            if (lane < 8) {
                int h = lane;
                float kx = sKp[le * 24 + h * 3], ky = sKp[le * 24 + h * 3 + 1], kz = sKp[le * 24 + h * 3 + 2];
                float pt = sHwn[h] * (sSq[h]
                           - 2.f * (sQsum[h * 3] * kx + sQsum[h * 3 + 1] * ky + sQsum[h * 3 + 2] * kz)
                           + 8.f * sKp2[le * 8 + h]);
                float logit = C1 * qkh + C2 * (bp[h] + sBB[h]) + pt
                            + INF_C * (sMaskSrc * md - 1.f);
                sLogit[le * 8 + h] = logit;
            }
        }
        __syncthreads();
        if (t < 8) {
            float cm = -3.0e38f;
            for (int le = 0; le < c; le++) cm = fmaxf(cm, sLogit[le * 8 + t]);
            float nm = fmaxf(sM[t], cm);
            sScale[t] = expf(sM[t] - nm);
            sM[t] = nm;
        }
        __syncthreads();
        {
            float sc = sScale[wid];
            za0 *= sc; za1 *= sc; za2 *= sc; za3 *= sc;
            if (t < 128) oAcc *= sScale[t >> 4];
            if (t < 24)  pAcc *= sScale[t / 3];
            if (t < 8)   sAcc *= sScale[t];
        }
        if (t < c * 8) sLogit[t] = expf(sLogit[t] - sM[t & 7]);
        __syncthreads();
#pragma unroll 2
        for (int le = 0; le < c; le++) {
            float w = sLogit[le * 8 + wid];
            float4 zv = *(const float4*)&sZ[le * 128 + lane * 4];
            za0 += w * zv.x; za1 += w * zv.y; za2 += w * zv.z; za3 += w * zv.w;
            if (t < 128) oAcc += sLogit[le * 8 + (t >> 4)] * sK[le * 128 + t];
            if (t < 24)  pAcc += sLogit[le * 8 + t / 3] * sKp[le * 24 + t];
            if (t < 8)   sAcc += sLogit[le * 8 + t];
        }
        __syncthreads();
    }

    float* sWdz  = bufA;
    float* sAccZ = bufA + 4096;
    float* sF    = bufA + 5120;
    float* sAccO = bufA + 5536;
    float* sAccP = bufA + 5664;
    float* sSv   = bufA + 5688;
    float* sInv  = bufA + 5696;
    float* sSa   = bufA + 5704;

    ((float4*)sAccZ)[t] = make_float4(za0, za1, za2, za3);
    if (t < 128) sAccO[t] = oAcc;
    if (t < 24)  sAccP[t] = pAcc;
    if (t < 8)   sSv[t] = sAcc;
#pragma unroll
    for (int r = 0; r < 4; r++)
        ((float4*)sWdz)[t + r * 256] = ((const float4*)Wdz)[t + r * 256];
    __syncthreads();
    if (t < 8) {
        float inv = 1.f / (sSv[t] + 1e-16f);
        sInv[t] = inv;
        sSa[t] = sSv[t] * inv;
    }
    __syncthreads();
    if (t < 128) sF[t] = sAccO[t] * sInv[t >> 4];
    if (t < 8) {
        int h = t;
        float gx = sAccP[h * 3 + 0] * sInv[h] - sT[0];
        float gy = sAccP[h * 3 + 1] * sInv[h] - sT[1];
        float gz = sAccP[h * 3 + 2] * sInv[h] - sT[2];
        float lx = sR[0] * gx + sR[3] * gy + sR[6] * gz;
        float ly = sR[1] * gx + sR[4] * gy + sR[7] * gz;
        float lz = sR[2] * gx + sR[5] * gy + sR[8] * gz;
        sF[128 + h] = lx; sF[136 + h] = ly; sF[144 + h] = lz;
        sF[152 + h] = sqrtf(lx * lx + ly * ly + lz * lz + 1e-8f);
    }
    {
        int h = wid, j = lane;
        float dot = 0.f;
#pragma unroll 8
        for (int cc = 0; cc < 128; cc++) dot += sAccZ[h * 128 + cc] * sWdz[cc * 32 + j];
        sF[160 + t] = dot * sInv[h] + sSa[h] * bdz[j];
    }
    __syncthreads();
    for (int idx = t; idx < 416; idx += 256)
        g_feats[(size_t)i * 416 + idx] = sF[idx];
}

// -------- launch --------
extern "C" void kernel_launch(void* const* d_in, const int* in_sizes, int n_in,
                              void* d_out, int out_size) {
    const float* frame_s = (const float*)d_in[0];
    const float* tfn     = (const float*)d_in[1];
    const float* z       = (const float*)d_in[2];
    const int*   ei      = (const int*)d_in[3];
    const float* mask    = (const float*)d_in[4];
    const float* rot     = (const float*)d_in[5];
    const float* trans   = (const float*)d_in[6];
    const float* Wq      = (const float*)d_in[7];
    const float* bq      = (const float*)d_in[8];
    const float* Wks     = (const float*)d_in[9];
    const float* Wkv     = (const float*)d_in[10];
    const float* Wqp     = (const float*)d_in[11];
    const float* bqp     = (const float*)d_in[12];
    const float* Wb      = (const float*)d_in[13];
    const float* bb      = (const float*)d_in[14];
    const float* Wdz     = (const float*)d_in[15];
    const float* bdz     = (const float*)d_in[16];
    const float* hw      = (const float*)d_in[17];
    const float* Wout    = (const float*)d_in[18];
    const float* bout    = (const float*)d_in[19];
    float* out = (float*)d_out;

    void *pq, *pqp, *pkv, *pfeats;
    cudaGetSymbolAddress(&pq, g_q);
    cudaGetSymbolAddress(&pqp, g_qp);
    cudaGetSymbolAddress(&pkv, g_kv);
    cudaGetSymbolAddress(&pfeats, g_feats);

    zero_int_kernel<<<(N_NODES + 255) / 256, 256>>>();
    hist_kernel<<<(E_EDGES + 255) / 256, 256>>>(ei);
    scan_kernel<<<1, 1024>>>();
    scatter_kernel<<<(E_EDGES + 255) / 256, 256>>>(ei);

    dim3 blk(256);
    int gy = (N_NODES + 127) / 128;   // 157
    sgemm_kernel<<<dim3(1, gy), blk>>>(frame_s, Wq,  bq,   (float*)pq,     N_NODES, 128, 384, 384);
    sgemm_kernel<<<dim3(2, gy), blk>>>(frame_s, Wqp, bqp,  (float*)pqp,    N_NODES, 192, 384, 384);
    sgemm_kernel<<<dim3(1, gy), blk>>>(tfn,     Wks, 0,    (float*)pkv,    N_NODES, 128, 128, 176);
    nodeprep_kernel<<<N_NODES, 64>>>(tfn, Wkv, rot, trans);
    edge_kernel<<<N_NODES, 256>>>(z, ei, mask, rot, trans, Wb, bb, Wdz, bdz, hw);
    sgemm_kernel<<<dim3(3, gy), blk>>>((const float*)pfeats, Wout, bout, out, N_NODES, 384, 416, 416);
}